// round 5
// baseline (speedup 1.0000x reference)
#include <cuda_runtime.h>

// YoloV1Loss: pred/label (16384, 30, 7, 7) fp32 -> scalar fp32.
// Smem-staged streaming: each block bulk-loads a 4-batch tile of both tensors
// with float4 coalesced loads, computes 196 cells from smem, then joins a
// deterministic two-level reduction (ticket/last-block, self-resetting).

#define BLOCK 256
#define NB    4                                     // batches per block tile
static constexpr int BATCH  = 16384;
static constexpr int NCH    = 30;
static constexpr int NCOL   = 7;
static constexpr int SPAT   = 49;
static constexpr int CHSTR  = SPAT;
static constexpr int BSTR   = NCH * SPAT;           // 1470
static constexpr int TILE_F = NB * BSTR;            // 5880 floats
static constexpr int TILE_V = TILE_F / 4;           // 1470 float4 (exact)
static constexpr int CELLS  = NB * SPAT;            // 196
static constexpr int GRID   = BATCH / NB;           // 4096

__device__ float        g_partials[GRID];
__device__ unsigned int g_count = 0;

__device__ __forceinline__ float iou_calc(float ax1, float ay1, float ax2, float ay2,
                                          float bx1, float by1, float bx2, float by2) {
    float iw = fmaxf(fminf(ax2, bx2) - fmaxf(ax1, bx1), 0.0f);
    float ih = fmaxf(fminf(ay2, by2) - fmaxf(ay1, by1), 0.0f);
    float inter = iw * ih;
    float area_a = (ax2 - ax1) * (ay2 - ay1);
    float area_b = (bx2 - bx1) * (by2 - by1);
    return inter / (area_a + area_b - inter + 1e-10f);
}

__global__ void __launch_bounds__(BLOCK) yolo_loss_fused(
    const float* __restrict__ pred, const float* __restrict__ label,
    float* __restrict__ out) {
    __shared__ float sp[TILE_F];
    __shared__ float sl[TILE_F];

    // ---- Stage tile: pure coalesced float4 stream ----
    {
        const float4* p4 = reinterpret_cast<const float4*>(pred)  + (size_t)blockIdx.x * TILE_V;
        const float4* l4 = reinterpret_cast<const float4*>(label) + (size_t)blockIdx.x * TILE_V;
        float4* sp4 = reinterpret_cast<float4*>(sp);
        float4* sl4 = reinterpret_cast<float4*>(sl);
        #pragma unroll
        for (int i = threadIdx.x; i < TILE_V; i += BLOCK) {
            sp4[i] = __ldg(p4 + i);
            sl4[i] = __ldg(l4 + i);
        }
    }
    __syncthreads();

    // ---- Compute: one cell per thread (threads 196..255 idle) ----
    float acc = 0.0f;
    if (threadIdx.x < CELLS) {
        int bl = threadIdx.x / SPAT;          // local batch 0..3
        int s  = threadIdx.x - bl * SPAT;     // spatial cell 0..48
        int row = s / NCOL;
        int col = s - row * NCOL;

        const float* pp = sp + bl * BSTR + s;
        const float* ll = sl + bl * BSTR + s;

        float p[10], lb[9];
        #pragma unroll
        for (int c = 0; c < 10; c++) p[c]  = pp[c * CHSTR];
        #pragma unroll
        for (int c = 0; c < 9;  c++) lb[c] = ll[c * CHSTR];
        float lb4 = lb[4];

        float class_l = 0.0f;
        #pragma unroll
        for (int c = 10; c < NCH; c++) {
            float d = pp[c * CHSTR] - ll[c * CHSTR];
            class_l = fmaf(d, d, class_l);
        }

        const float inv = 1.0f / (float)NCOL;
        float fc = (float)col, fr = (float)row;

        float cx = (p[0] + fc) * inv, cy = (p[1] + fr) * inv;
        float a1x1 = cx - 0.5f * p[2], a1y1 = cy - 0.5f * p[3];
        float a1x2 = cx + 0.5f * p[2], a1y2 = cy + 0.5f * p[3];
        cx = (p[5] + fc) * inv; cy = (p[6] + fr) * inv;
        float a2x1 = cx - 0.5f * p[7], a2y1 = cy - 0.5f * p[8];
        float a2x2 = cx + 0.5f * p[7], a2y2 = cy + 0.5f * p[8];
        cx = (lb[0] + fc) * inv; cy = (lb[1] + fr) * inv;
        float lx1 = cx - 0.5f * lb[2], ly1 = cy - 0.5f * lb[3];
        float lx2 = cx + 0.5f * lb[2], ly2 = cy + 0.5f * lb[3];

        float iou1 = iou_calc(a1x1, a1y1, a1x2, a1y2, lx1, ly1, lx2, ly2);
        float iou2 = iou_calc(a2x1, a2y1, a2x2, a2y2, lx1, ly1, lx2, ly2);
        bool choose1 = (iou1 >= iou2);

        float d0 = p[0] - lb[0], d1 = p[1] - lb[1];
        float sw1 = sqrtf(p[2]) - sqrtf(lb[2]);
        float sh1 = sqrtf(p[3]) - sqrtf(lb[3]);
        float coord1 = 5.0f * (d0 * d0 + d1 * d1) + sw1 * sw1 + sh1 * sh1;

        float e0 = p[5] - lb[5], e1 = p[6] - lb[6];
        float sw2 = sqrtf(p[7]) - sqrtf(lb[7]);
        float sh2 = sqrtf(p[8]) - sqrtf(lb[8]);
        float coord2 = 5.0f * (e0 * e0 + e1 * e1) + sw2 * sw2 + sh2 * sh2;

        float o1 = p[4] - iou1; float obj1 = o1 * o1;
        float o2 = p[9] - iou2; float obj2 = o2 * o2;

        float coord      = choose1 ? coord1 : coord2;
        float obj_conf   = choose1 ? obj1   : obj2;
        float noobj_conf = 0.5f * (choose1 ? obj2 : obj1);

        float obj_cell = coord + obj_conf + noobj_conf + class_l;
        float nsum = p[4] + p[9];
        float noobj_cell = 0.5f * nsum * nsum;

        acc = (lb4 == 1.0f) ? obj_cell : noobj_cell;
    }

    // ---- Deterministic block reduction ----
    #pragma unroll
    for (int off = 16; off > 0; off >>= 1)
        acc += __shfl_down_sync(0xFFFFFFFFu, acc, off);

    __shared__ float warp_sums[BLOCK / 32];
    if ((threadIdx.x & 31) == 0) warp_sums[threadIdx.x >> 5] = acc;
    __syncthreads();

    __shared__ bool is_last;
    if (threadIdx.x < 32) {
        float v = (threadIdx.x < BLOCK / 32) ? warp_sums[threadIdx.x] : 0.0f;
        #pragma unroll
        for (int off = 16; off > 0; off >>= 1)
            v += __shfl_down_sync(0xFFFFFFFFu, v, off);
        if (threadIdx.x == 0) {
            g_partials[blockIdx.x] = v;
            __threadfence();
            unsigned int ticket = atomicAdd(&g_count, 1u);
            is_last = (ticket == GRID - 1);
        }
    }
    __syncthreads();

    // ---- Final block: deterministic fixed-order sum of partials ----
    if (is_last) {
        float s = 0.0f;
        for (int i = threadIdx.x; i < GRID; i += BLOCK)
            s += g_partials[i];
        #pragma unroll
        for (int off = 16; off > 0; off >>= 1)
            s += __shfl_down_sync(0xFFFFFFFFu, s, off);

        __shared__ float fw[BLOCK / 32];
        if ((threadIdx.x & 31) == 0) fw[threadIdx.x >> 5] = s;
        __syncthreads();
        if (threadIdx.x < 32) {
            float v = (threadIdx.x < BLOCK / 32) ? fw[threadIdx.x] : 0.0f;
            #pragma unroll
            for (int off = 16; off > 0; off >>= 1)
                v += __shfl_down_sync(0xFFFFFFFFu, v, off);
            if (threadIdx.x == 0) {
                out[0] = v * (1.0f / (float)BATCH);
                g_count = 0;   // reset for next graph replay
            }
        }
    }
}

extern "C" void kernel_launch(void* const* d_in, const int* in_sizes, int n_in,
                              void* d_out, int out_size) {
    const float* pred  = (const float*)d_in[0];
    const float* label = (const float*)d_in[1];
    float* out = (float*)d_out;
    yolo_loss_fused<<<GRID, BLOCK>>>(pred, label, out);
}

// round 6
// speedup vs baseline: 1.1046x; 1.1046x over previous
#include <cuda_runtime.h>

// YoloV1Loss: pred/label (16384, 30, 7, 7) fp32 -> scalar fp32.
// Fused streaming reduction, direct coalesced LDG (R4 structure).
// Register-lean for 6 blocks/SM: class channels stream-accumulated (2 accs),
// IOU computed in unscaled cell coordinates (the /7 cancels in inter/union).

#define BLOCK 256
#define CPT   2                                    // cells per thread
static constexpr int BATCH  = 16384;
static constexpr int NCH    = 30;
static constexpr int NCOL   = 7;
static constexpr int SPAT   = 49;
static constexpr int CHSTR  = SPAT;
static constexpr int BSTR   = NCH * SPAT;          // 1470
static constexpr int NCELLS = BATCH * SPAT;        // 802816
static constexpr int GRID   = NCELLS / (BLOCK * CPT); // 1568 exactly

__device__ float        g_partials[GRID];
__device__ unsigned int g_count = 0;

__device__ __forceinline__ float iou_calc(float ax1, float ay1, float ax2, float ay2,
                                          float bx1, float by1, float bx2, float by2) {
    float iw = fmaxf(fminf(ax2, bx2) - fmaxf(ax1, bx1), 0.0f);
    float ih = fmaxf(fminf(ay2, by2) - fmaxf(ay1, by1), 0.0f);
    float inter = iw * ih;
    float area_a = (ax2 - ax1) * (ay2 - ay1);
    float area_b = (bx2 - bx1) * (by2 - by1);
    return inter / (area_a + area_b - inter + 1e-10f);
}

__device__ __forceinline__ float cell_loss(const float* __restrict__ pred,
                                           const float* __restrict__ label,
                                           int t) {
    int b = t / SPAT;
    int s = t - b * SPAT;
    int row = s / NCOL;
    int col = s - row * NCOL;

    const float* pp = pred  + (size_t)b * BSTR + s;
    const float* ll = label + (size_t)b * BSTR + s;

    // Live header channels only: pred 0..9, label 0..8.
    float p[10], lb[9];
    #pragma unroll
    for (int c = 0; c < 10; c++) p[c]  = __ldg(pp + c * CHSTR);
    #pragma unroll
    for (int c = 0; c < 9;  c++) lb[c] = __ldg(ll + c * CHSTR);

    // Stream-accumulate class loss (channels 10..29), 2 independent chains.
    float cl0 = 0.0f, cl1 = 0.0f;
    #pragma unroll
    for (int c = 10; c < NCH; c += 2) {
        float d0 = __ldg(pp + c * CHSTR)       - __ldg(ll + c * CHSTR);
        float d1 = __ldg(pp + (c + 1) * CHSTR) - __ldg(ll + (c + 1) * CHSTR);
        cl0 = fmaf(d0, d0, cl0);
        cl1 = fmaf(d1, d1, cl1);
    }
    float class_l = cl0 + cl1;

    // IOU in unscaled cell coordinates: (x+col) with half-extent 3.5*w.
    // All coords are 7x the reference's; inter & union scale by 49 -> cancels
    // (up to the 1e-10 eps, relative error ~1e-9).
    float fc = (float)col, fr = (float)row;

    float cx = p[0] + fc, cy = p[1] + fr;
    float hw = 3.5f * p[2], hh = 3.5f * p[3];
    float a1x1 = cx - hw, a1y1 = cy - hh, a1x2 = cx + hw, a1y2 = cy + hh;
    cx = p[5] + fc; cy = p[6] + fr;
    hw = 3.5f * p[7]; hh = 3.5f * p[8];
    float a2x1 = cx - hw, a2y1 = cy - hh, a2x2 = cx + hw, a2y2 = cy + hh;
    cx = lb[0] + fc; cy = lb[1] + fr;
    hw = 3.5f * lb[2]; hh = 3.5f * lb[3];
    float lx1 = cx - hw, ly1 = cy - hh, lx2 = cx + hw, ly2 = cy + hh;

    float iou1 = iou_calc(a1x1, a1y1, a1x2, a1y2, lx1, ly1, lx2, ly2);
    float iou2 = iou_calc(a2x1, a2y1, a2x2, a2y2, lx1, ly1, lx2, ly2);
    bool choose1 = (iou1 >= iou2);

    float d0 = p[0] - lb[0], d1 = p[1] - lb[1];
    float sw1 = sqrtf(p[2]) - sqrtf(lb[2]);
    float sh1 = sqrtf(p[3]) - sqrtf(lb[3]);
    float coord1 = 5.0f * (d0 * d0 + d1 * d1) + sw1 * sw1 + sh1 * sh1;

    float e0 = p[5] - lb[5], e1 = p[6] - lb[6];
    float sw2 = sqrtf(p[7]) - sqrtf(lb[7]);
    float sh2 = sqrtf(p[8]) - sqrtf(lb[8]);
    float coord2 = 5.0f * (e0 * e0 + e1 * e1) + sw2 * sw2 + sh2 * sh2;

    float o1 = p[4] - iou1; float obj1 = o1 * o1;
    float o2 = p[9] - iou2; float obj2 = o2 * o2;

    float coord      = choose1 ? coord1 : coord2;
    float obj_conf   = choose1 ? obj1   : obj2;
    float noobj_conf = 0.5f * (choose1 ? obj2 : obj1);

    float obj_cell = coord + obj_conf + noobj_conf + class_l;
    float nsum = p[4] + p[9];
    float noobj_cell = 0.5f * nsum * nsum;

    return (lb[4] == 1.0f) ? obj_cell : noobj_cell;
}

__global__ void __launch_bounds__(BLOCK, 6) yolo_loss_fused(
    const float* __restrict__ pred, const float* __restrict__ label,
    float* __restrict__ out) {
    float acc = 0.0f;
    #pragma unroll
    for (int i = 0; i < CPT; i++) {
        int t = (i * GRID + blockIdx.x) * BLOCK + threadIdx.x;
        acc += cell_loss(pred, label, t);
    }

    // Deterministic block reduction.
    #pragma unroll
    for (int off = 16; off > 0; off >>= 1)
        acc += __shfl_down_sync(0xFFFFFFFFu, acc, off);

    __shared__ float warp_sums[BLOCK / 32];
    if ((threadIdx.x & 31) == 0) warp_sums[threadIdx.x >> 5] = acc;
    __syncthreads();

    __shared__ bool is_last;
    if (threadIdx.x < 32) {
        float v = (threadIdx.x < BLOCK / 32) ? warp_sums[threadIdx.x] : 0.0f;
        #pragma unroll
        for (int off = 16; off > 0; off >>= 1)
            v += __shfl_down_sync(0xFFFFFFFFu, v, off);
        if (threadIdx.x == 0) {
            g_partials[blockIdx.x] = v;
            __threadfence();
            unsigned int ticket = atomicAdd(&g_count, 1u);
            is_last = (ticket == GRID - 1);
        }
    }
    __syncthreads();

    // Final block: deterministic fixed-order sum of all partials.
    if (is_last) {
        float s = 0.0f;
        for (int i = threadIdx.x; i < GRID; i += BLOCK)
            s += g_partials[i];
        #pragma unroll
        for (int off = 16; off > 0; off >>= 1)
            s += __shfl_down_sync(0xFFFFFFFFu, s, off);

        __shared__ float fw[BLOCK / 32];
        if ((threadIdx.x & 31) == 0) fw[threadIdx.x >> 5] = s;
        __syncthreads();
        if (threadIdx.x < 32) {
            float v = (threadIdx.x < BLOCK / 32) ? fw[threadIdx.x] : 0.0f;
            #pragma unroll
            for (int off = 16; off > 0; off >>= 1)
                v += __shfl_down_sync(0xFFFFFFFFu, v, off);
            if (threadIdx.x == 0) {
                out[0] = v * (1.0f / (float)BATCH);
                g_count = 0;   // reset for next graph replay
            }
        }
    }
}

extern "C" void kernel_launch(void* const* d_in, const int* in_sizes, int n_in,
                              void* d_out, int out_size) {
    const float* pred  = (const float*)d_in[0];
    const float* label = (const float*)d_in[1];
    float* out = (float*)d_out;
    yolo_loss_fused<<<GRID, BLOCK>>>(pred, label, out);
}

// round 8
// speedup vs baseline: 1.1661x; 1.0557x over previous
#include <cuda_runtime.h>
#include <cstdint>

// YoloV1Loss: pred/label (16384, 30, 7, 7) fp32 -> scalar fp32.
// Persistent blocks + 1D TMA bulk-copy (cp.async.bulk) 4-stage mbarrier
// pipeline streaming contiguous 2-batch tiles into smem; compute from smem.
// Deterministic two-level reduction (ticket/last-block, self-resetting).

#define BLOCK 256
static constexpr int BATCH   = 16384;
static constexpr int NCH     = 30;
static constexpr int NCOL    = 7;
static constexpr int SPAT    = 49;
static constexpr int CHSTR   = SPAT;
static constexpr int BSTR    = NCH * SPAT;            // 1470 floats/batch
static constexpr int NB      = 2;                     // batches per tile
static constexpr int TILE_F  = NB * BSTR;             // 2940 floats per tensor
static constexpr int TILE_B  = TILE_F * 4;            // 11760 bytes per tensor
static constexpr int STAGE_F = 2 * TILE_F;            // 5880 floats (pred+label)
static constexpr int STAGE_B = 2 * TILE_B;            // 23520 bytes
static constexpr int NSTAGES = 4;
static constexpr int SMEM_DYN = NSTAGES * STAGE_B;    // 94080 bytes
static constexpr int NTILES  = BATCH / NB;            // 8192
static constexpr int GRID    = 296;                   // 2 blocks/SM x 148
static constexpr int CELLS   = NB * SPAT;             // 98

__device__ float        g_partials[GRID];
__device__ unsigned int g_count = 0;

__device__ __forceinline__ uint32_t smem_u32(const void* p) {
    uint32_t a;
    asm("{ .reg .u64 t; cvta.to.shared.u64 t, %1; cvt.u32.u64 %0, t; }"
        : "=r"(a) : "l"(p));
    return a;
}

__device__ __forceinline__ void mbar_init(uint32_t mbar, uint32_t count) {
    asm volatile("mbarrier.init.shared.b64 [%0], %1;" :: "r"(mbar), "r"(count) : "memory");
}

__device__ __forceinline__ void mbar_wait(uint32_t mbar, uint32_t parity) {
    asm volatile(
        "{\n\t.reg .pred P;\n\t"
        "WAIT_%=:\n\t"
        "mbarrier.try_wait.parity.acquire.cta.shared::cta.b64 P, [%0], %1, 0x989680;\n\t"
        "@P bra.uni DONE_%=;\n\t"
        "bra.uni WAIT_%=;\n\t"
        "DONE_%=:\n\t}"
        :: "r"(mbar), "r"(parity) : "memory");
}

// Issue one tile: expect_tx + two 1D bulk copies (pred, label) into stage.
__device__ __forceinline__ void issue_tile(uint32_t stage_smem, uint32_t mbar,
                                           const float* __restrict__ pred,
                                           const float* __restrict__ label,
                                           int tile) {
    const char* srcp = (const char*)pred  + (size_t)tile * TILE_B;
    const char* srcl = (const char*)label + (size_t)tile * TILE_B;
    asm volatile("mbarrier.arrive.expect_tx.shared::cta.b64 _, [%0], %1;"
                 :: "r"(mbar), "r"((uint32_t)STAGE_B) : "memory");
    asm volatile("cp.async.bulk.shared::cluster.global.mbarrier::complete_tx::bytes "
                 "[%0], [%1], %2, [%3];"
                 :: "r"(stage_smem), "l"(srcp), "r"((uint32_t)TILE_B), "r"(mbar) : "memory");
    asm volatile("cp.async.bulk.shared::cluster.global.mbarrier::complete_tx::bytes "
                 "[%0], [%1], %2, [%3];"
                 :: "r"(stage_smem + TILE_B), "l"(srcl), "r"((uint32_t)TILE_B), "r"(mbar) : "memory");
}

__device__ __forceinline__ float iou_calc(float ax1, float ay1, float ax2, float ay2,
                                          float bx1, float by1, float bx2, float by2) {
    float iw = fmaxf(fminf(ax2, bx2) - fmaxf(ax1, bx1), 0.0f);
    float ih = fmaxf(fminf(ay2, by2) - fmaxf(ay1, by1), 0.0f);
    float inter = iw * ih;
    float area_a = (ax2 - ax1) * (ay2 - ay1);
    float area_b = (bx2 - bx1) * (by2 - by1);
    return inter / (area_a + area_b - inter + 1e-10f);
}

// Per-cell loss from smem tile. pp/ll point at channel-0 of this cell.
__device__ __forceinline__ float cell_loss(const float* __restrict__ pp,
                                           const float* __restrict__ ll,
                                           int row, int col) {
    float p[10], lb[9];
    #pragma unroll
    for (int c = 0; c < 10; c++) p[c]  = pp[c * CHSTR];
    #pragma unroll
    for (int c = 0; c < 9;  c++) lb[c] = ll[c * CHSTR];

    float cl0 = 0.0f, cl1 = 0.0f;
    #pragma unroll
    for (int c = 10; c < NCH; c += 2) {
        float d0 = pp[c * CHSTR]       - ll[c * CHSTR];
        float d1 = pp[(c + 1) * CHSTR] - ll[(c + 1) * CHSTR];
        cl0 = fmaf(d0, d0, cl0);
        cl1 = fmaf(d1, d1, cl1);
    }
    float class_l = cl0 + cl1;

    const float inv = 1.0f / (float)NCOL;
    float fc = (float)col, fr = (float)row;

    float cx = (p[0] + fc) * inv, cy = (p[1] + fr) * inv;
    float a1x1 = cx - 0.5f * p[2], a1y1 = cy - 0.5f * p[3];
    float a1x2 = cx + 0.5f * p[2], a1y2 = cy + 0.5f * p[3];
    cx = (p[5] + fc) * inv; cy = (p[6] + fr) * inv;
    float a2x1 = cx - 0.5f * p[7], a2y1 = cy - 0.5f * p[8];
    float a2x2 = cx + 0.5f * p[7], a2y2 = cy + 0.5f * p[8];
    cx = (lb[0] + fc) * inv; cy = (lb[1] + fr) * inv;
    float lx1 = cx - 0.5f * lb[2], ly1 = cy - 0.5f * lb[3];
    float lx2 = cx + 0.5f * lb[2], ly2 = cy + 0.5f * lb[3];

    float iou1 = iou_calc(a1x1, a1y1, a1x2, a1y2, lx1, ly1, lx2, ly2);
    float iou2 = iou_calc(a2x1, a2y1, a2x2, a2y2, lx1, ly1, lx2, ly2);
    bool choose1 = (iou1 >= iou2);

    float d0 = p[0] - lb[0], d1 = p[1] - lb[1];
    float sw1 = sqrtf(p[2]) - sqrtf(lb[2]);
    float sh1 = sqrtf(p[3]) - sqrtf(lb[3]);
    float coord1 = 5.0f * (d0 * d0 + d1 * d1) + sw1 * sw1 + sh1 * sh1;

    float e0 = p[5] - lb[5], e1 = p[6] - lb[6];
    float sw2 = sqrtf(p[7]) - sqrtf(lb[7]);
    float sh2 = sqrtf(p[8]) - sqrtf(lb[8]);
    float coord2 = 5.0f * (e0 * e0 + e1 * e1) + sw2 * sw2 + sh2 * sh2;

    float o1 = p[4] - iou1; float obj1 = o1 * o1;
    float o2 = p[9] - iou2; float obj2 = o2 * o2;

    float coord      = choose1 ? coord1 : coord2;
    float obj_conf   = choose1 ? obj1   : obj2;
    float noobj_conf = 0.5f * (choose1 ? obj2 : obj1);

    float obj_cell = coord + obj_conf + noobj_conf + class_l;
    float nsum = p[4] + p[9];
    float noobj_cell = 0.5f * nsum * nsum;

    return (lb[4] == 1.0f) ? obj_cell : noobj_cell;
}

__global__ void __launch_bounds__(BLOCK) yolo_loss_tma(
    const float* __restrict__ pred, const float* __restrict__ label,
    float* __restrict__ out) {
    extern __shared__ float smem[];
    __shared__ __align__(8) unsigned long long mbar_store[NSTAGES];

    const uint32_t smem_base = smem_u32(smem);
    const uint32_t mbar_base = smem_u32(mbar_store);
    const int tid = threadIdx.x;

    if (tid == 0) {
        #pragma unroll
        for (int s = 0; s < NSTAGES; s++) mbar_init(mbar_base + s * 8, 1);
    }
    __syncthreads();

    // Prologue: fill the ring.
    if (tid == 0) {
        #pragma unroll
        for (int j = 0; j < NSTAGES; j++) {
            int tile = blockIdx.x + j * GRID;
            if (tile < NTILES)
                issue_tile(smem_base + j * STAGE_B, mbar_base + j * 8, pred, label, tile);
        }
    }

    // Pre-compute this thread's cell geometry (fixed across tiles).
    int bl = 0, s2 = 0, row = 0, col = 0;
    if (tid < CELLS) {
        bl = tid / SPAT;
        s2 = tid - bl * SPAT;
        row = s2 / NCOL;
        col = s2 - row * NCOL;
    }

    float acc = 0.0f;
    int j = 0;
    for (int tile = blockIdx.x; tile < NTILES; tile += GRID, j++) {
        int st = j & (NSTAGES - 1);
        uint32_t parity = (j >> 2) & 1;
        mbar_wait(mbar_base + st * 8, parity);

        if (tid < CELLS) {
            const float* base = smem + st * STAGE_F;
            const float* pp = base + bl * BSTR + s2;
            const float* ll = base + TILE_F + bl * BSTR + s2;
            acc += cell_loss(pp, ll, row, col);
        }
        __syncthreads();   // all readers done with this stage

        int nxt = tile + NSTAGES * GRID;
        if (tid == 0 && nxt < NTILES)
            issue_tile(smem_base + st * STAGE_B, mbar_base + st * 8, pred, label, nxt);
    }

    // ---- Deterministic block reduction ----
    #pragma unroll
    for (int off = 16; off > 0; off >>= 1)
        acc += __shfl_down_sync(0xFFFFFFFFu, acc, off);

    __shared__ float warp_sums[BLOCK / 32];
    if ((tid & 31) == 0) warp_sums[tid >> 5] = acc;
    __syncthreads();

    __shared__ bool is_last;
    if (tid < 32) {
        float v = (tid < BLOCK / 32) ? warp_sums[tid] : 0.0f;
        #pragma unroll
        for (int off = 16; off > 0; off >>= 1)
            v += __shfl_down_sync(0xFFFFFFFFu, v, off);
        if (tid == 0) {
            g_partials[blockIdx.x] = v;
            __threadfence();
            unsigned int ticket = atomicAdd(&g_count, 1u);
            is_last = (ticket == GRID - 1);
        }
    }
    __syncthreads();

    if (is_last) {
        float s = (tid < GRID) ? g_partials[tid] : 0.0f;
        if (tid + BLOCK < GRID) s += g_partials[tid + BLOCK];
        #pragma unroll
        for (int off = 16; off > 0; off >>= 1)
            s += __shfl_down_sync(0xFFFFFFFFu, s, off);

        __shared__ float fw[BLOCK / 32];
        if ((tid & 31) == 0) fw[tid >> 5] = s;
        __syncthreads();
        if (tid < 32) {
            float v = (tid < BLOCK / 32) ? fw[tid] : 0.0f;
            #pragma unroll
            for (int off = 16; off > 0; off >>= 1)
                v += __shfl_down_sync(0xFFFFFFFFu, v, off);
            if (tid == 0) {
                out[0] = v * (1.0f / (float)BATCH);
                g_count = 0;   // reset for next graph replay
            }
        }
    }
}

extern "C" void kernel_launch(void* const* d_in, const int* in_sizes, int n_in,
                              void* d_out, int out_size) {
    const float* pred  = (const float*)d_in[0];
    const float* label = (const float*)d_in[1];
    float* out = (float*)d_out;

    cudaFuncSetAttribute(yolo_loss_tma,
                         cudaFuncAttributeMaxDynamicSharedMemorySize, SMEM_DYN);
    yolo_loss_tma<<<GRID, BLOCK, SMEM_DYN>>>(pred, label, out);
}